// round 3
// baseline (speedup 1.0000x reference)
#include <cuda_runtime.h>
#include <cuda_bf16.h>

// GCN 2-layer + mean pool.
// Inputs (metadata order):
//  0: x          [100000, 5]   f32
//  1: edge_index [2, 3200000]  int32 (harness converts int64 -> int32); row0=src, row1=dst
//  2: batch      [100000]      int32 (sorted)
//  3: W1 [5,16] f32   4: b1 [16] f32
//  5: W2 [16,16] f32  6: b2 [16] f32
// Output: [512, 16] f32
//
// Pipeline:
//  K0 init:    pool/cnt zero, deg=1 (self loop), feat = x @ W1
//  K1 deg:     deg[dst] += 1 per edge (float atomics)
//  K2 norm:    dinv = rsqrt(deg); acc = dinv^2 * feat   (self-loop term)
//  K3 edge L1: acc[dst] += dinv[src]*dinv[dst] * feat[src]   (16 thr/edge)
//  K4 mid:     h1 = relu(acc+b1); feat = h1 @ W2 (shfl matvec); acc = dinv^2*feat
//  K5 edge L2: same as K3
//  K6 pool:    h2 = relu(acc+b2); pool[batch[i]] += h2; cnt[batch[i]] += 1
//  K7 out:     out = pool / max(cnt,1)

#define MAX_NODES 100000
#define MAX_GRAPHS 512

__device__ float g_deg [MAX_NODES];
__device__ float g_dinv[MAX_NODES];
__device__ float g_feat[MAX_NODES * 16];   // xW1, then h1@W2
__device__ float g_acc [MAX_NODES * 16];   // accumulators per layer
__device__ float g_pool[MAX_GRAPHS * 16];
__device__ float g_cnt [MAX_GRAPHS];

// ---------------------------------------------------------------- K0
__global__ void k_init(const float* __restrict__ x,
                       const float* __restrict__ W1,
                       int N, int G) {
    __shared__ float sW1[80];
    if (threadIdx.x < 80) sW1[threadIdx.x] = W1[threadIdx.x];
    __syncthreads();
    int t = blockIdx.x * 256 + threadIdx.x;
    if (t < G * 16) g_pool[t] = 0.f;
    if (t < G)      g_cnt[t]  = 0.f;
    if (t >= N * 16) return;
    int i = t >> 4, f = t & 15;
    if (f == 0) g_deg[i] = 1.0f;              // self loop
    float acc = 0.f;
#pragma unroll
    for (int k = 0; k < 5; k++)
        acc += __ldg(&x[i * 5 + k]) * sW1[k * 16 + f];
    g_feat[t] = acc;
}

// ---------------------------------------------------------------- K1
__global__ void k_deg(const int* __restrict__ dst, int E, int N) {
    int e = blockIdx.x * 256 + threadIdx.x;
    if (e >= E) return;
    int d = dst[e];
    if ((unsigned)d < (unsigned)N)
        atomicAdd(&g_deg[d], 1.0f);
}

// ---------------------------------------------------------------- K2
__global__ void k_norm(int N) {
    int t = blockIdx.x * 256 + threadIdx.x;
    if (t >= N * 16) return;
    int i = t >> 4, f = t & 15;
    float di = rsqrtf(g_deg[i]);              // deg >= 1 always
    if (f == 0) g_dinv[i] = di;
    g_acc[t] = di * di * g_feat[t];
}

// ---------------------------------------------------------------- K3/K5
// 16 threads per edge: thread f handles feature f.
// Gather g_feat[src*16+f] is a coalesced 64B group (L2-resident),
// atomic target g_acc[dst*16+f] likewise 16 consecutive floats.
__global__ void k_edge(const int* __restrict__ src,
                       const int* __restrict__ dst, int E, int N) {
    unsigned t = blockIdx.x * 256u + threadIdx.x;
    unsigned e = t >> 4;
    if (e >= (unsigned)E) return;
    int f = t & 15;
    int s = src[e];
    int d = dst[e];
    if ((unsigned)s >= (unsigned)N || (unsigned)d >= (unsigned)N) return;
    float norm = g_dinv[s] * g_dinv[d];
    atomicAdd(&g_acc[d * 16 + f], norm * g_feat[s * 16 + f]);
}

// ---------------------------------------------------------------- K4
__global__ void k_mid(const float* __restrict__ b1,
                      const float* __restrict__ W2, int N) {
    __shared__ float sW2[256];
    __shared__ float sb1[16];
    if (threadIdx.x < 256) sW2[threadIdx.x] = W2[threadIdx.x];
    if (threadIdx.x < 16)  sb1[threadIdx.x] = b1[threadIdx.x];
    __syncthreads();
    int t = blockIdx.x * 256 + threadIdx.x;
    int tc = t < N * 16 ? t : N * 16 - 1;     // clamp: keep warp intact for shfl
    int i = tc >> 4, f = tc & 15;
    float h = fmaxf(g_acc[tc] + sb1[f], 0.f); // h1
    float acc = 0.f;
#pragma unroll
    for (int k = 0; k < 16; k++) {
        float hk = __shfl_sync(0xffffffffu, h, k, 16);
        acc += hk * sW2[k * 16 + f];
    }
    if (t >= N * 16) return;
    float di = g_dinv[i];
    g_feat[t] = acc;                          // h1 @ W2
    g_acc[t]  = di * di * acc;                // self-loop term, layer 2
}

// ---------------------------------------------------------------- K6
__global__ void k_pool(const int* __restrict__ batch,
                       const float* __restrict__ b2, int N, int G) {
    __shared__ float sb2[16];
    if (threadIdx.x < 16) sb2[threadIdx.x] = b2[threadIdx.x];
    __syncthreads();
    int t = blockIdx.x * 256 + threadIdx.x;
    if (t >= N * 16) return;
    int i = t >> 4, f = t & 15;
    float h = fmaxf(g_acc[t] + sb2[f], 0.f);  // h2
    int g = batch[i];
    if ((unsigned)g >= (unsigned)G) return;
    atomicAdd(&g_pool[g * 16 + f], h);
    if (f == 0) atomicAdd(&g_cnt[g], 1.0f);
}

// ---------------------------------------------------------------- K7
__global__ void k_out(float* __restrict__ out, int G) {
    int t = blockIdx.x * 256 + threadIdx.x;
    if (t >= G * 16) return;
    out[t] = g_pool[t] / fmaxf(g_cnt[t >> 4], 1.0f);
}

// ----------------------------------------------------------------
extern "C" void kernel_launch(void* const* d_in, const int* in_sizes, int n_in,
                              void* d_out, int out_size) {
    const float* x     = (const float*)d_in[0];
    const int*   ei    = (const int*)d_in[1];
    const int*   batch = (const int*)d_in[2];
    const float* W1    = (const float*)d_in[3];
    const float* b1    = (const float*)d_in[4];
    const float* W2    = (const float*)d_in[5];
    const float* b2    = (const float*)d_in[6];
    float*       out   = (float*)d_out;

    int N = in_sizes[0] / 5;        // 100000
    int E = in_sizes[1] / 2;        // 3200000
    int G = out_size / 16;          // 512

    const int* src = ei;
    const int* dst = ei + E;

    int gN16 = (N * 16 + 255) / 256;
    int gE   = (E + 255) / 256;
    int gE16 = (int)(((long long)E * 16 + 255) / 256);
    int gG16 = (G * 16 + 255) / 256;

    k_init<<<gN16, 256>>>(x, W1, N, G);
    k_deg <<<gE,   256>>>(dst, E, N);
    k_norm<<<gN16, 256>>>(N);
    k_edge<<<gE16, 256>>>(src, dst, E, N);
    k_mid <<<gN16, 256>>>(b1, W2, N);
    k_edge<<<gE16, 256>>>(src, dst, E, N);
    k_pool<<<gN16, 256>>>(batch, b2, N, G);
    k_out <<<gG16, 256>>>(out, G);
}

// round 4
// speedup vs baseline: 1.6596x; 1.6596x over previous
#include <cuda_runtime.h>
#include <cuda_bf16.h>

// GCN 2-layer + mean pool — CSR pull-mode (no float atomics in aggregation).
// Inputs: 0:x[100000,5] f32  1:edge_index[2,3.2M] i32  2:batch[100000] i32
//         3:W1[5,16] 4:b1[16] 5:W2[16,16] 6:b2[16]   Output: [512,16] f32

#define MAX_NODES  100000
#define MAX_EDGES  3200000
#define MAX_GRAPHS 512
#define SCAN_BLK   1024

__device__ float g_dinv[MAX_NODES];
__device__ __align__(16) float g_feat[MAX_NODES * 16]; // xW1, then h1@W2
__device__ __align__(16) float g_acc [MAX_NODES * 16];
__device__ float g_pool[MAX_GRAPHS * 16];
__device__ float g_cnt [MAX_GRAPHS];
__device__ int   g_ecnt  [MAX_NODES];       // in-degree (edges only)
__device__ int   g_rowptr[MAX_NODES + 1];
__device__ int   g_pos   [MAX_NODES];
__device__ int   g_esrc  [MAX_EDGES];       // src ids grouped by dst
__device__ int   g_bsum  [1024];
__device__ int   g_boff  [1024];
__device__ int   g_total;

// ---------------------------------------------------------------- K0: feat = x@W1, zero state
__global__ void k_init(const float* __restrict__ x,
                       const float* __restrict__ W1, int N, int G) {
    __shared__ float sW1[80];
    if (threadIdx.x < 80) sW1[threadIdx.x] = W1[threadIdx.x];
    __syncthreads();
    int t = blockIdx.x * 256 + threadIdx.x;
    if (t < G * 16) g_pool[t] = 0.f;
    if (t < G)      g_cnt[t]  = 0.f;
    if (t >= N * 16) return;
    int i = t >> 4, f = t & 15;
    if (f == 0) g_ecnt[i] = 0;
    float acc = 0.f;
#pragma unroll
    for (int k = 0; k < 5; k++)
        acc += __ldg(&x[i * 5 + k]) * sW1[k * 16 + f];
    g_feat[t] = acc;
}

// ---------------------------------------------------------------- K1: in-degree histogram
__global__ void k_hist(const int* __restrict__ src,
                       const int* __restrict__ dst, int E, int N) {
    int e = blockIdx.x * 256 + threadIdx.x;
    if (e >= E) return;
    int s = src[e], d = dst[e];
    if ((unsigned)s >= (unsigned)N || (unsigned)d >= (unsigned)N) return;
    atomicAdd(&g_ecnt[d], 1);
}

// ---------------------------------------------------------------- K2: per-block scan
__global__ void k_scanA(int N) {
    __shared__ int s[SCAN_BLK];
    int tid = threadIdx.x;
    int i = blockIdx.x * SCAN_BLK + tid;
    int v = (i < N) ? g_ecnt[i] : 0;
    s[tid] = v; __syncthreads();
    for (int off = 1; off < SCAN_BLK; off <<= 1) {
        int a = (tid >= off) ? s[tid - off] : 0;
        __syncthreads();
        s[tid] += a;
        __syncthreads();
    }
    if (i < N) g_rowptr[i] = s[tid] - v;           // local exclusive
    if (tid == SCAN_BLK - 1) g_bsum[blockIdx.x] = s[tid];
}

// ---------------------------------------------------------------- K3: scan block sums
__global__ void k_scanB(int nb) {
    __shared__ int s[1024];
    int tid = threadIdx.x;
    int v = (tid < nb) ? g_bsum[tid] : 0;
    s[tid] = v; __syncthreads();
    for (int off = 1; off < 1024; off <<= 1) {
        int a = (tid >= off) ? s[tid - off] : 0;
        __syncthreads();
        s[tid] += a;
        __syncthreads();
    }
    g_boff[tid] = s[tid] - v;                      // exclusive
    if (tid == nb - 1) g_total = s[tid];
}

// ---------------------------------------------------------------- K4: finalize rowptr + dinv
__global__ void k_scanC(int N) {
    int i = blockIdx.x * 256 + threadIdx.x;
    if (i > N) return;
    if (i == N) { g_rowptr[N] = g_total; return; }
    int r = g_rowptr[i] + g_boff[i >> 10];         // >>10 == /SCAN_BLK
    g_rowptr[i] = r;
    g_pos[i]    = r;
    g_dinv[i]   = rsqrtf((float)(g_ecnt[i] + 1));  // +1 = self loop
}

// ---------------------------------------------------------------- K5: scatter edges into CSR
__global__ void k_scatter(const int* __restrict__ src,
                          const int* __restrict__ dst, int E, int N) {
    int e = blockIdx.x * 256 + threadIdx.x;
    if (e >= E) return;
    int s = src[e], d = dst[e];
    if ((unsigned)s >= (unsigned)N || (unsigned)d >= (unsigned)N) return;
    int p = atomicAdd(&g_pos[d], 1);
    g_esrc[p] = s;
}

// ---------------------------------------------------------------- pull core: 4 thr/node, float4
__device__ __forceinline__ float4 pull_node(int node, int lane,
                                            const float4* __restrict__ f4) {
    int j   = g_rowptr[node];
    int end = g_rowptr[node + 1];
    float4 acc = make_float4(0.f, 0.f, 0.f, 0.f);
    for (; j + 4 <= end; j += 4) {
        int s0 = g_esrc[j], s1 = g_esrc[j+1], s2 = g_esrc[j+2], s3 = g_esrc[j+3];
        float d0 = g_dinv[s0], d1 = g_dinv[s1], d2 = g_dinv[s2], d3 = g_dinv[s3];
        float4 v0 = f4[s0*4 + lane], v1 = f4[s1*4 + lane];
        float4 v2 = f4[s2*4 + lane], v3 = f4[s3*4 + lane];
        acc.x += d0*v0.x + d1*v1.x + d2*v2.x + d3*v3.x;
        acc.y += d0*v0.y + d1*v1.y + d2*v2.y + d3*v3.y;
        acc.z += d0*v0.z + d1*v1.z + d2*v2.z + d3*v3.z;
        acc.w += d0*v0.w + d1*v1.w + d2*v2.w + d3*v3.w;
    }
    for (; j < end; j++) {
        int s = g_esrc[j];
        float ds = g_dinv[s];
        float4 v = f4[s*4 + lane];
        acc.x += ds*v.x; acc.y += ds*v.y; acc.z += ds*v.z; acc.w += ds*v.w;
    }
    float dd = g_dinv[node];
    float4 sv = f4[node*4 + lane];
    float dd2 = dd * dd;
    return make_float4(dd*acc.x + dd2*sv.x, dd*acc.y + dd2*sv.y,
                       dd*acc.z + dd2*sv.z, dd*acc.w + dd2*sv.w);
}

// ---------------------------------------------------------------- K6: layer-1 aggregation
__global__ void k_pull1(int N) {
    int t = blockIdx.x * 256 + threadIdx.x;
    int node = t >> 2;
    if (node >= N) return;
    int lane = t & 3;
    float4 r = pull_node(node, lane, (const float4*)g_feat);
    ((float4*)g_acc)[node*4 + lane] = r;
}

// ---------------------------------------------------------------- K7: h1=relu(acc+b1); feat=h1@W2
__global__ void k_mid(const float* __restrict__ b1,
                      const float* __restrict__ W2, int N) {
    __shared__ float sW2[256];
    __shared__ float sb1[16];
    if (threadIdx.x < 256) sW2[threadIdx.x] = W2[threadIdx.x];
    if (threadIdx.x < 16)  sb1[threadIdx.x] = b1[threadIdx.x];
    __syncthreads();
    int t = blockIdx.x * 256 + threadIdx.x;
    int tc = t < N * 16 ? t : N * 16 - 1;          // keep warp intact for shfl
    int f = tc & 15;
    float h = fmaxf(g_acc[tc] + sb1[f], 0.f);
    float acc = 0.f;
#pragma unroll
    for (int k = 0; k < 16; k++) {
        float hk = __shfl_sync(0xffffffffu, h, k, 16);
        acc += hk * sW2[k * 16 + f];
    }
    if (t >= N * 16) return;
    g_feat[t] = acc;
}

// ---------------------------------------------------------------- K8: layer-2 aggregation + pool
__global__ void k_pull2(const int* __restrict__ batch,
                        const float* __restrict__ b2, int N, int G) {
    int t = blockIdx.x * 256 + threadIdx.x;
    int node = t >> 2;
    if (node >= N) return;
    int lane = t & 3;
    float4 r  = pull_node(node, lane, (const float4*)g_feat);
    float4 bv = __ldg(&((const float4*)b2)[lane]);
    float hx = fmaxf(r.x + bv.x, 0.f);
    float hy = fmaxf(r.y + bv.y, 0.f);
    float hz = fmaxf(r.z + bv.z, 0.f);
    float hw = fmaxf(r.w + bv.w, 0.f);
    int g = batch[node];
    if ((unsigned)g >= (unsigned)G) return;
    float* p = &g_pool[g * 16 + lane * 4];
    atomicAdd(p + 0, hx);
    atomicAdd(p + 1, hy);
    atomicAdd(p + 2, hz);
    atomicAdd(p + 3, hw);
    if (lane == 0) atomicAdd(&g_cnt[g], 1.0f);
}

// ---------------------------------------------------------------- K9: mean
__global__ void k_out(float* __restrict__ out, int G) {
    int t = blockIdx.x * 256 + threadIdx.x;
    if (t >= G * 16) return;
    out[t] = g_pool[t] / fmaxf(g_cnt[t >> 4], 1.0f);
}

// ----------------------------------------------------------------
extern "C" void kernel_launch(void* const* d_in, const int* in_sizes, int n_in,
                              void* d_out, int out_size) {
    const float* x     = (const float*)d_in[0];
    const int*   ei    = (const int*)d_in[1];
    const int*   batch = (const int*)d_in[2];
    const float* W1    = (const float*)d_in[3];
    const float* b1    = (const float*)d_in[4];
    const float* W2    = (const float*)d_in[5];
    const float* b2    = (const float*)d_in[6];
    float*       out   = (float*)d_out;

    int N = in_sizes[0] / 5;        // 100000
    int E = in_sizes[1] / 2;        // 3200000
    int G = out_size / 16;          // 512

    const int* src = ei;
    const int* dst = ei + E;

    int gN16 = (N * 16 + 255) / 256;
    int gE   = (E + 255) / 256;
    int gN4  = (N * 4 + 255) / 256;
    int gG16 = (G * 16 + 255) / 256;
    int nb   = (N + SCAN_BLK - 1) / SCAN_BLK;

    k_init   <<<gN16, 256>>>(x, W1, N, G);
    k_hist   <<<gE,   256>>>(src, dst, E, N);
    k_scanA  <<<nb,   SCAN_BLK>>>(N);
    k_scanB  <<<1,    1024>>>(nb);
    k_scanC  <<<(N + 256) / 256 + 1, 256>>>(N);
    k_scatter<<<gE,   256>>>(src, dst, E, N);
    k_pull1  <<<gN4,  256>>>(N);
    k_mid    <<<gN16, 256>>>(b1, W2, N);
    k_pull2  <<<gN4,  256>>>(batch, b2, N, G);
    k_out    <<<gG16, 256>>>(out, G);
}

// round 5
// speedup vs baseline: 1.8090x; 1.0900x over previous
#include <cuda_runtime.h>
#include <cuda_bf16.h>

// GCN 2-layer + mean pool — CSR pull-mode, mid-layer matvec fused into pull1.
// Inputs: 0:x[100000,5] f32  1:edge_index[2,3.2M] i32  2:batch[100000] i32
//         3:W1[5,16] 4:b1[16] 5:W2[16,16] 6:b2[16]   Output: [512,16] f32

#define MAX_NODES  100000
#define MAX_EDGES  3200000
#define MAX_GRAPHS 512
#define SCAN_BLK   1024

__device__ float g_dinv[MAX_NODES];
__device__ __align__(16) float g_feat[MAX_NODES * 16]; // layer-1 input feats (xW1)
__device__ __align__(16) float g_acc [MAX_NODES * 16]; // layer-2 input feats (h1@W2)
__device__ float g_pool[MAX_GRAPHS * 16];
__device__ float g_cnt [MAX_GRAPHS];
__device__ int   g_ecnt  [MAX_NODES];
__device__ int   g_rowptr[MAX_NODES + 1];
__device__ int   g_pos   [MAX_NODES];
__device__ int   g_esrc  [MAX_EDGES];
__device__ int   g_bsum  [128];
__device__ int   g_boff  [128];
__device__ int   g_total;

// ---------------------------------------------------------------- K0: feat = x@W1, zero state
__global__ void k_init(const float* __restrict__ x,
                       const float* __restrict__ W1, int N, int G) {
    __shared__ float sW1[80];
    if (threadIdx.x < 80) sW1[threadIdx.x] = W1[threadIdx.x];
    __syncthreads();
    int t = blockIdx.x * 256 + threadIdx.x;
    if (t < G * 16) g_pool[t] = 0.f;
    if (t < G)      g_cnt[t]  = 0.f;
    if (t >= N * 16) return;
    int i = t >> 4, f = t & 15;
    if (f == 0) g_ecnt[i] = 0;
    float acc = 0.f;
#pragma unroll
    for (int k = 0; k < 5; k++)
        acc += __ldg(&x[i * 5 + k]) * sW1[k * 16 + f];
    g_feat[t] = acc;
}

// ---------------------------------------------------------------- K1: in-degree histogram
__global__ void k_hist(const int* __restrict__ dst, int E, int N) {
    int e = blockIdx.x * 256 + threadIdx.x;
    if (e >= E) return;
    int d = dst[e];
    if ((unsigned)d < (unsigned)N) atomicAdd(&g_ecnt[d], 1);
}

// ---------------------------------------------------------------- K2: per-block scan (shfl)
__global__ void k_scanA(int N) {
    __shared__ int wsum[32];
    int tid = threadIdx.x;
    int i = blockIdx.x * SCAN_BLK + tid;
    int v = (i < N) ? g_ecnt[i] : 0;
    int xv = v;
#pragma unroll
    for (int o = 1; o < 32; o <<= 1) {
        int y = __shfl_up_sync(0xffffffffu, xv, o);
        if ((tid & 31) >= o) xv += y;
    }
    if ((tid & 31) == 31) wsum[tid >> 5] = xv;
    __syncthreads();
    if (tid < 32) {
        int w = wsum[tid];
#pragma unroll
        for (int o = 1; o < 32; o <<= 1) {
            int y = __shfl_up_sync(0xffffffffu, w, o);
            if (tid >= o) w += y;
        }
        wsum[tid] = w;
    }
    __syncthreads();
    int base = (tid >= 32) ? wsum[(tid >> 5) - 1] : 0;
    int incl = xv + base;
    if (i < N) g_rowptr[i] = incl - v;             // local exclusive
    if (tid == SCAN_BLK - 1) g_bsum[blockIdx.x] = incl;
}

// ---------------------------------------------------------------- K3: scan block sums (<=128)
__global__ void k_scanB(int nb) {
    __shared__ int wsum[4];
    int tid = threadIdx.x;
    int v = (tid < nb) ? g_bsum[tid] : 0;
    int xv = v;
#pragma unroll
    for (int o = 1; o < 32; o <<= 1) {
        int y = __shfl_up_sync(0xffffffffu, xv, o);
        if ((tid & 31) >= o) xv += y;
    }
    if ((tid & 31) == 31) wsum[tid >> 5] = xv;
    __syncthreads();
    int base = 0;
#pragma unroll
    for (int w = 0; w < 4; w++)
        if ((tid >> 5) > w) base += wsum[w];
    int incl = xv + base;
    g_boff[tid] = incl - v;                        // exclusive
    if (tid == nb - 1) g_total = incl;
}

// ---------------------------------------------------------------- K4: finalize rowptr + dinv
__global__ void k_scanC(int N) {
    int i = blockIdx.x * 256 + threadIdx.x;
    if (i > N) return;
    if (i == N) { g_rowptr[N] = g_total; return; }
    int r = g_rowptr[i] + g_boff[i >> 10];
    g_rowptr[i] = r;
    g_pos[i]    = r;
    g_dinv[i]   = rsqrtf((float)(g_ecnt[i] + 1));  // +1 = self loop
}

// ---------------------------------------------------------------- K5: scatter edges into CSR
__global__ void k_scatter(const int* __restrict__ src,
                          const int* __restrict__ dst, int E, int N) {
    int e = blockIdx.x * 256 + threadIdx.x;
    if (e >= E) return;
    int s = src[e], d = dst[e];
    if ((unsigned)s >= (unsigned)N || (unsigned)d >= (unsigned)N) return;
    int p = atomicAdd(&g_pos[d], 1);
    g_esrc[p] = s;
}

// ---------------------------------------------------------------- pull core: 4 thr/node, float4
__device__ __forceinline__ float4 pull_node(int node, int lane,
                                            const float4* __restrict__ f4) {
    int j   = g_rowptr[node];
    int end = g_rowptr[node + 1];
    float4 acc = make_float4(0.f, 0.f, 0.f, 0.f);
    for (; j + 4 <= end; j += 4) {
        int s0 = g_esrc[j], s1 = g_esrc[j+1], s2 = g_esrc[j+2], s3 = g_esrc[j+3];
        float d0 = g_dinv[s0], d1 = g_dinv[s1], d2 = g_dinv[s2], d3 = g_dinv[s3];
        float4 v0 = f4[s0*4 + lane], v1 = f4[s1*4 + lane];
        float4 v2 = f4[s2*4 + lane], v3 = f4[s3*4 + lane];
        acc.x += d0*v0.x + d1*v1.x + d2*v2.x + d3*v3.x;
        acc.y += d0*v0.y + d1*v1.y + d2*v2.y + d3*v3.y;
        acc.z += d0*v0.z + d1*v1.z + d2*v2.z + d3*v3.z;
        acc.w += d0*v0.w + d1*v1.w + d2*v2.w + d3*v3.w;
    }
    for (; j < end; j++) {
        int s = g_esrc[j];
        float ds = g_dinv[s];
        float4 v = f4[s*4 + lane];
        acc.x += ds*v.x; acc.y += ds*v.y; acc.z += ds*v.z; acc.w += ds*v.w;
    }
    float dd = g_dinv[node];
    float4 sv = f4[node*4 + lane];
    float dd2 = dd * dd;
    return make_float4(dd*acc.x + dd2*sv.x, dd*acc.y + dd2*sv.y,
                       dd*acc.z + dd2*sv.z, dd*acc.w + dd2*sv.w);
}

// ---------------------------------------------------------------- K6: layer-1 pull + relu + @W2
// Writes h1@W2 into g_acc (NOT g_feat — other blocks still gather g_feat).
__global__ void k_pull1(const float* __restrict__ b1,
                        const float* __restrict__ W2, int N) {
    __shared__ float sW2[256];
    __shared__ float sb1[16];
    if (threadIdx.x < 256) sW2[threadIdx.x] = W2[threadIdx.x];
    if (threadIdx.x < 16)  sb1[threadIdx.x] = b1[threadIdx.x];
    __syncthreads();
    int t = blockIdx.x * 256 + threadIdx.x;
    int node = t >> 2;
    bool valid = node < N;
    int nodec = valid ? node : N - 1;              // keep shfl groups intact
    int lane = t & 3;
    float4 r = pull_node(nodec, lane, (const float4*)g_feat);
    // h1 = relu(r + b1)
    float4 h;
    h.x = fmaxf(r.x + sb1[lane*4+0], 0.f);
    h.y = fmaxf(r.y + sb1[lane*4+1], 0.f);
    h.z = fmaxf(r.z + sb1[lane*4+2], 0.f);
    h.w = fmaxf(r.w + sb1[lane*4+3], 0.f);
    // feat2[f] = sum_k h[k] * W2[k][f], f in [lane*4, lane*4+4)
    float4 res = make_float4(0.f, 0.f, 0.f, 0.f);
    int fb = lane * 4;
#pragma unroll
    for (int g = 0; g < 4; g++) {
        float hx = __shfl_sync(0xffffffffu, h.x, g, 4);
        float hy = __shfl_sync(0xffffffffu, h.y, g, 4);
        float hz = __shfl_sync(0xffffffffu, h.z, g, 4);
        float hw = __shfl_sync(0xffffffffu, h.w, g, 4);
        int kb = g * 4;
        const float* w0 = &sW2[(kb+0)*16 + fb];
        const float* w1 = &sW2[(kb+1)*16 + fb];
        const float* w2 = &sW2[(kb+2)*16 + fb];
        const float* w3 = &sW2[(kb+3)*16 + fb];
        res.x += hx*w0[0] + hy*w1[0] + hz*w2[0] + hw*w3[0];
        res.y += hx*w0[1] + hy*w1[1] + hz*w2[1] + hw*w3[1];
        res.z += hx*w0[2] + hy*w1[2] + hz*w2[2] + hw*w3[2];
        res.w += hx*w0[3] + hy*w1[3] + hz*w2[3] + hw*w3[3];
    }
    if (valid) ((float4*)g_acc)[node*4 + lane] = res;
}

// ---------------------------------------------------------------- K7: layer-2 pull + relu + pool
__global__ void k_pull2(const int* __restrict__ batch,
                        const float* __restrict__ b2, int N, int G) {
    int t = blockIdx.x * 256 + threadIdx.x;
    int node = t >> 2;
    if (node >= N) return;
    int lane = t & 3;
    float4 r  = pull_node(node, lane, (const float4*)g_acc);
    float4 bv = __ldg(&((const float4*)b2)[lane]);
    float hx = fmaxf(r.x + bv.x, 0.f);
    float hy = fmaxf(r.y + bv.y, 0.f);
    float hz = fmaxf(r.z + bv.z, 0.f);
    float hw = fmaxf(r.w + bv.w, 0.f);
    int g = batch[node];
    if ((unsigned)g >= (unsigned)G) return;
    float* p = &g_pool[g * 16 + lane * 4];
    atomicAdd(p + 0, hx);
    atomicAdd(p + 1, hy);
    atomicAdd(p + 2, hz);
    atomicAdd(p + 3, hw);
    if (lane == 0) atomicAdd(&g_cnt[g], 1.0f);
}

// ---------------------------------------------------------------- K8: mean
__global__ void k_out(float* __restrict__ out, int G) {
    int t = blockIdx.x * 256 + threadIdx.x;
    if (t >= G * 16) return;
    out[t] = g_pool[t] / fmaxf(g_cnt[t >> 4], 1.0f);
}

// ----------------------------------------------------------------
extern "C" void kernel_launch(void* const* d_in, const int* in_sizes, int n_in,
                              void* d_out, int out_size) {
    const float* x     = (const float*)d_in[0];
    const int*   ei    = (const int*)d_in[1];
    const int*   batch = (const int*)d_in[2];
    const float* W1    = (const float*)d_in[3];
    const float* b1    = (const float*)d_in[4];
    const float* W2    = (const float*)d_in[5];
    const float* b2    = (const float*)d_in[6];
    float*       out   = (float*)d_out;

    int N = in_sizes[0] / 5;        // 100000
    int E = in_sizes[1] / 2;        // 3200000
    int G = out_size / 16;          // 512

    const int* src = ei;
    const int* dst = ei + E;

    int gN16 = (N * 16 + 255) / 256;
    int gE   = (E + 255) / 256;
    int gN4  = (N * 4 + 255) / 256;
    int gG16 = (G * 16 + 255) / 256;
    int nb   = (N + SCAN_BLK - 1) / SCAN_BLK;   // 98 (<=128)

    k_init   <<<gN16, 256>>>(x, W1, N, G);
    k_hist   <<<gE,   256>>>(dst, E, N);
    k_scanA  <<<nb,   SCAN_BLK>>>(N);
    k_scanB  <<<1,    128>>>(nb);
    k_scanC  <<<(N + 1 + 255) / 256, 256>>>(N);
    k_scatter<<<gE,   256>>>(src, dst, E, N);
    k_pull1  <<<gN4,  256>>>(b1, W2, N);
    k_pull2  <<<gN4,  256>>>(batch, b2, N, G);
    k_out    <<<gG16, 256>>>(out, G);
}

// round 7
// speedup vs baseline: 1.9727x; 1.0905x over previous
#include <cuda_runtime.h>
#include <cuda_bf16.h>

// GCN 2-layer + mean pool — CSR pull-mode with dinv-prescaled features.
// Inputs: 0:x[100000,5] f32  1:edge_index[2,3.2M] i32  2:batch[100000] i32
//         3:W1[5,16] 4:b1[16] 5:W2[16,16] 6:b2[16]   Output: [512,16] f32
//
// Math: out_i = dinv_i * ( sum_{s->i} sfeat_s + sfeat_i ) + b, sfeat = dinv*feat.
// g_ecnt is left zeroed by k_out at the END of each run (static-init zero on run 1),
// which lets k_init and k_hist share one launch.

#define MAX_NODES  100000
#define MAX_EDGES  3200000
#define MAX_GRAPHS 512
#define SCAN_BLK   1024

__device__ float g_dinv[MAX_NODES];
__device__ __align__(16) float g_feat[MAX_NODES * 16]; // xW1, then dinv*(xW1) after scanC
__device__ __align__(16) float g_acc [MAX_NODES * 16]; // dinv*(h1@W2)
__device__ float g_pool[MAX_GRAPHS * 16];
__device__ float g_cnt [MAX_GRAPHS];
__device__ int   g_ecnt  [MAX_NODES];
__device__ int   g_rowptr[MAX_NODES + 1];
__device__ int   g_pos   [MAX_NODES];
__device__ int   g_esrc  [MAX_EDGES];
__device__ int   g_bsum  [128];
__device__ int   g_boff  [128];
__device__ int   g_total;

// ---------------------------------------------------------------- K0: init (feat=x@W1) + hist
__global__ void k_init_hist(const float* __restrict__ x,
                            const float* __restrict__ W1,
                            const int* __restrict__ dst,
                            int N, int G, int E, int nInitBlk) {
    if ((int)blockIdx.x < nInitBlk) {
        __shared__ float sW1[80];
        if (threadIdx.x < 80) sW1[threadIdx.x] = W1[threadIdx.x];
        __syncthreads();
        int t = blockIdx.x * 256 + threadIdx.x;
        if (t < G * 16) g_pool[t] = 0.f;
        if (t < G)      g_cnt[t]  = 0.f;
        if (t >= N * 16) return;
        int i = t >> 4, f = t & 15;
        float acc = 0.f;
#pragma unroll
        for (int k = 0; k < 5; k++)
            acc += __ldg(&x[i * 5 + k]) * sW1[k * 16 + f];
        g_feat[t] = acc;
    } else {
        int e = (blockIdx.x - nInitBlk) * 256 + threadIdx.x;
        if (e >= E) return;
        int d = dst[e];
        if ((unsigned)d < (unsigned)N) atomicAdd(&g_ecnt[d], 1);  // g_ecnt pre-zeroed
    }
}

// ---------------------------------------------------------------- K1: per-block scan (shfl)
__global__ void k_scanA(int N) {
    __shared__ int wsum[32];
    int tid = threadIdx.x;
    int i = blockIdx.x * SCAN_BLK + tid;
    int v = (i < N) ? g_ecnt[i] : 0;
    int xv = v;
#pragma unroll
    for (int o = 1; o < 32; o <<= 1) {
        int y = __shfl_up_sync(0xffffffffu, xv, o);
        if ((tid & 31) >= o) xv += y;
    }
    if ((tid & 31) == 31) wsum[tid >> 5] = xv;
    __syncthreads();
    if (tid < 32) {
        int w = wsum[tid];
#pragma unroll
        for (int o = 1; o < 32; o <<= 1) {
            int y = __shfl_up_sync(0xffffffffu, w, o);
            if (tid >= o) w += y;
        }
        wsum[tid] = w;
    }
    __syncthreads();
    int base = (tid >= 32) ? wsum[(tid >> 5) - 1] : 0;
    int incl = xv + base;
    if (i < N) g_rowptr[i] = incl - v;             // local exclusive
    if (tid == SCAN_BLK - 1) g_bsum[blockIdx.x] = incl;
}

// ---------------------------------------------------------------- K2: scan block sums (<=128)
__global__ void k_scanB(int nb) {
    __shared__ int wsum[4];
    int tid = threadIdx.x;
    int v = (tid < nb) ? g_bsum[tid] : 0;
    int xv = v;
#pragma unroll
    for (int o = 1; o < 32; o <<= 1) {
        int y = __shfl_up_sync(0xffffffffu, xv, o);
        if ((tid & 31) >= o) xv += y;
    }
    if ((tid & 31) == 31) wsum[tid >> 5] = xv;
    __syncthreads();
    int base = 0;
#pragma unroll
    for (int w = 0; w < 4; w++)
        if ((tid >> 5) > w) base += wsum[w];
    int incl = xv + base;
    g_boff[tid] = incl - v;                        // exclusive
    if (tid == nb - 1) g_total = incl;
}

// ---------------------------------------------------------------- K3: finalize rowptr + dinv + prescale feat
__global__ void k_scanC(int N) {
    int t = blockIdx.x * 256 + threadIdx.x;
    if (t == 0) g_rowptr[N] = g_total;
    int i = t >> 2;
    if (i >= N) return;
    int lane = t & 3;
    float di = rsqrtf((float)(g_ecnt[i] + 1));     // +1 = self loop
    if (lane == 0) {
        int r = g_rowptr[i] + g_boff[i >> 10];
        g_rowptr[i] = r;
        g_pos[i]    = r;
        g_dinv[i]   = di;
    }
    float4 v = ((const float4*)g_feat)[i * 4 + lane];
    v.x *= di; v.y *= di; v.z *= di; v.w *= di;
    ((float4*)g_feat)[i * 4 + lane] = v;
}

// ---------------------------------------------------------------- K4: scatter edges into CSR
__global__ void k_scatter(const int* __restrict__ src,
                          const int* __restrict__ dst, int E, int N) {
    int e = blockIdx.x * 256 + threadIdx.x;
    if (e >= E) return;
    int s = src[e], d = dst[e];
    if ((unsigned)s >= (unsigned)N || (unsigned)d >= (unsigned)N) return;
    int p = atomicAdd(&g_pos[d], 1);
    g_esrc[p] = s;
}

// ---------------------------------------------------------------- pull core: 4 thr/node, float4
// f4 holds PRE-SCALED features. Returns dinv_node * (sum_neighbors + self).
__device__ __forceinline__ float4 pull_node(int node, int lane,
                                            const float4* __restrict__ f4) {
    int j   = g_rowptr[node];
    int end = g_rowptr[node + 1];
    float4 a0 = make_float4(0.f, 0.f, 0.f, 0.f);
    float4 a1 = make_float4(0.f, 0.f, 0.f, 0.f);
    for (; j + 8 <= end; j += 8) {
        int s0 = g_esrc[j+0], s1 = g_esrc[j+1], s2 = g_esrc[j+2], s3 = g_esrc[j+3];
        int s4 = g_esrc[j+4], s5 = g_esrc[j+5], s6 = g_esrc[j+6], s7 = g_esrc[j+7];
        float4 v0 = f4[s0*4 + lane], v1 = f4[s1*4 + lane];
        float4 v2 = f4[s2*4 + lane], v3 = f4[s3*4 + lane];
        float4 v4 = f4[s4*4 + lane], v5 = f4[s5*4 + lane];
        float4 v6 = f4[s6*4 + lane], v7 = f4[s7*4 + lane];
        a0.x += v0.x + v1.x + v2.x + v3.x;  a1.x += v4.x + v5.x + v6.x + v7.x;
        a0.y += v0.y + v1.y + v2.y + v3.y;  a1.y += v4.y + v5.y + v6.y + v7.y;
        a0.z += v0.z + v1.z + v2.z + v3.z;  a1.z += v4.z + v5.z + v6.z + v7.z;
        a0.w += v0.w + v1.w + v2.w + v3.w;  a1.w += v4.w + v5.w + v6.w + v7.w;
    }
    for (; j < end; j++) {
        int s = g_esrc[j];
        float4 v = f4[s*4 + lane];
        a0.x += v.x; a0.y += v.y; a0.z += v.z; a0.w += v.w;
    }
    float4 sv = f4[node*4 + lane];                 // self (pre-scaled)
    float dd = g_dinv[node];
    return make_float4(dd*(a0.x + a1.x + sv.x), dd*(a0.y + a1.y + sv.y),
                       dd*(a0.z + a1.z + sv.z), dd*(a0.w + a1.w + sv.w));
}

// ---------------------------------------------------------------- K5: layer-1 pull + relu + @W2, prescaled out
__global__ void k_pull1(const float* __restrict__ b1,
                        const float* __restrict__ W2, int N) {
    __shared__ float sW2[256];
    __shared__ float sb1[16];
    if (threadIdx.x < 256) sW2[threadIdx.x] = W2[threadIdx.x];
    if (threadIdx.x < 16)  sb1[threadIdx.x] = b1[threadIdx.x];
    __syncthreads();
    int t = blockIdx.x * 256 + threadIdx.x;
    int node = t >> 2;
    bool valid = node < N;
    int nodec = valid ? node : N - 1;              // keep shfl groups intact
    int lane = t & 3;
    float4 r = pull_node(nodec, lane, (const float4*)g_feat);
    float4 h;
    h.x = fmaxf(r.x + sb1[lane*4+0], 0.f);
    h.y = fmaxf(r.y + sb1[lane*4+1], 0.f);
    h.z = fmaxf(r.z + sb1[lane*4+2], 0.f);
    h.w = fmaxf(r.w + sb1[lane*4+3], 0.f);
    float4 res = make_float4(0.f, 0.f, 0.f, 0.f);
    int fb = lane * 4;
#pragma unroll
    for (int g = 0; g < 4; g++) {
        float hx = __shfl_sync(0xffffffffu, h.x, g, 4);
        float hy = __shfl_sync(0xffffffffu, h.y, g, 4);
        float hz = __shfl_sync(0xffffffffu, h.z, g, 4);
        float hw = __shfl_sync(0xffffffffu, h.w, g, 4);
        int kb = g * 4;
        const float* w0 = &sW2[(kb+0)*16 + fb];
        const float* w1 = &sW2[(kb+1)*16 + fb];
        const float* w2 = &sW2[(kb+2)*16 + fb];
        const float* w3 = &sW2[(kb+3)*16 + fb];
        res.x += hx*w0[0] + hy*w1[0] + hz*w2[0] + hw*w3[0];
        res.y += hx*w0[1] + hy*w1[1] + hz*w2[1] + hw*w3[1];
        res.z += hx*w0[2] + hy*w1[2] + hz*w2[2] + hw*w3[2];
        res.w += hx*w0[3] + hy*w1[3] + hz*w2[3] + hw*w3[3];
    }
    if (valid) {
        float dd = g_dinv[node];                   // prescale for layer-2 pull
        res.x *= dd; res.y *= dd; res.z *= dd; res.w *= dd;
        ((float4*)g_acc)[node*4 + lane] = res;
    }
}

// ---------------------------------------------------------------- K6: layer-2 pull + relu + pool
__global__ void k_pull2(const int* __restrict__ batch,
                        const float* __restrict__ b2, int N, int G) {
    int t = blockIdx.x * 256 + threadIdx.x;
    int node = t >> 2;
    if (node >= N) return;
    int lane = t & 3;
    float4 r  = pull_node(node, lane, (const float4*)g_acc);
    float4 bv = __ldg(&((const float4*)b2)[lane]);
    float hx = fmaxf(r.x + bv.x, 0.f);
    float hy = fmaxf(r.y + bv.y, 0.f);
    float hz = fmaxf(r.z + bv.z, 0.f);
    float hw = fmaxf(r.w + bv.w, 0.f);
    int g = batch[node];
    if ((unsigned)g >= (unsigned)G) return;
    float* p = &g_pool[g * 16 + lane * 4];
    atomicAdd(p + 0, hx);
    atomicAdd(p + 1, hy);
    atomicAdd(p + 2, hz);
    atomicAdd(p + 3, hw);
    if (lane == 0) atomicAdd(&g_cnt[g], 1.0f);
}

// ---------------------------------------------------------------- K7: mean + re-zero g_ecnt for next run
__global__ void k_out(float* __restrict__ out, int G, int N) {
    int t = blockIdx.x * 256 + threadIdx.x;
    if (t < N) g_ecnt[t] = 0;                      // leave zeroed for next launch
    if (t >= G * 16) return;
    out[t] = g_pool[t] / fmaxf(g_cnt[t >> 4], 1.0f);
}

// ----------------------------------------------------------------
extern "C" void kernel_launch(void* const* d_in, const int* in_sizes, int n_in,
                              void* d_out, int out_size) {
    const float* x     = (const float*)d_in[0];
    const int*   ei    = (const int*)d_in[1];
    const int*   batch = (const int*)d_in[2];
    const float* W1    = (const float*)d_in[3];
    const float* b1    = (const float*)d_in[4];
    const float* W2    = (const float*)d_in[5];
    const float* b2    = (const float*)d_in[6];
    float*       out   = (float*)d_out;

    int N = in_sizes[0] / 5;        // 100000
    int E = in_sizes[1] / 2;        // 3200000
    int G = out_size / 16;          // 512

    const int* src = ei;
    const int* dst = ei + E;

    int gN16 = (N * 16 + 255) / 256;
    int gE   = (E + 255) / 256;
    int gN4  = (N * 4 + 255) / 256;
    int nb   = (N + SCAN_BLK - 1) / SCAN_BLK;   // 98 (<=128)
    int gOut = (N + 255) / 256;                 // covers both N and G*16

    k_init_hist<<<gN16 + gE, 256>>>(x, W1, dst, N, G, E, gN16);
    k_scanA  <<<nb,   SCAN_BLK>>>(N);
    k_scanB  <<<1,    128>>>(nb);
    k_scanC  <<<gN4,  256>>>(N);
    k_scatter<<<gE,   256>>>(src, dst, E, N);
    k_pull1  <<<gN4,  256>>>(b1, W2, N);
    k_pull2  <<<gN4,  256>>>(batch, b2, N, G);
    k_out    <<<gOut, 256>>>(out, G, N);
}